// round 2
// baseline (speedup 1.0000x reference)
#include <cuda_runtime.h>
#include <cuda_bf16.h>

#define LIB     969     // 1 + 16 + 136 + 816
#define NODE    16
#define NT      256
#define ZSTRIDE 17      // pad so z[k] dynamic indexing is bank-conflict-free

// 8x packed f32x2 FMA: acc[0..7] (16 outputs) += v * coeff_row[0..15]
__device__ __forceinline__ void fma8(unsigned long long acc[8], float v, const float* cp) {
    unsigned long long vv;
    asm("mov.b64 %0, {%1, %1};" : "=l"(vv) : "f"(v));
    const ulonglong2* c2 = reinterpret_cast<const ulonglong2*>(cp);  // LDS.128, warp-uniform (broadcast)
    #pragma unroll
    for (int h = 0; h < 4; h++) {
        ulonglong2 c = c2[h];
        asm("fma.rn.f32x2 %0, %1, %2, %0;" : "+l"(acc[2*h])     : "l"(vv), "l"(c.x));
        asm("fma.rn.f32x2 %0, %1, %2, %0;" : "+l"(acc[2*h + 1]) : "l"(vv), "l"(c.y));
    }
}

extern __shared__ float smem_dyn[];

__global__ void __launch_bounds__(NT)
sindy_main_kernel(const float* __restrict__ z,
                  const float* __restrict__ coef,
                  const float* __restrict__ mask,
                  float* __restrict__ out, int N)
{
    float* sC = smem_dyn;                   // LIB*NODE = 15504 floats (60.6 KB)
    float* sZ = smem_dyn + LIB * NODE;      // NT*ZSTRIDE floats

    // Stage masked coefficients into smem
    for (int idx = threadIdx.x; idx < LIB * NODE; idx += NT)
        sC[idx] = coef[idx] * mask[idx];

    const int row = blockIdx.x * NT + threadIdx.x;
    float* zs = sZ + threadIdx.x * ZSTRIDE;
    if (row < N) {
        const float4* zr = reinterpret_cast<const float4*>(z + (size_t)row * 16);
        #pragma unroll
        for (int q = 0; q < 4; q++) {
            float4 t = zr[q];
            zs[4*q + 0] = t.x; zs[4*q + 1] = t.y;
            zs[4*q + 2] = t.z; zs[4*q + 3] = t.w;
        }
    }
    __syncthreads();
    if (row >= N) return;

    // acc = coefficient row of the constant feature "1"
    unsigned long long acc[8];
    {
        const ulonglong2* c0 = reinterpret_cast<const ulonglong2*>(sC);
        #pragma unroll
        for (int h = 0; h < 4; h++) { acc[2*h] = c0[h].x; acc[2*h + 1] = c0[h].y; }
    }

    const float* cp = sC + NODE;

    // linear terms: features 1..16
    #pragma unroll 1
    for (int i = 0; i < 16; i++) { fma8(acc, zs[i], cp); cp += NODE; }

    // pair terms: z_i * z_j, i <= j  (136 features, lexicographic like np.triu_indices)
    #pragma unroll 1
    for (int i = 0; i < 16; i++) {
        float zi = zs[i];
        #pragma unroll 1
        for (int j = i; j < 16; j++) { fma8(acc, zi * zs[j], cp); cp += NODE; }
    }

    // triple terms: z_i * z_j * z_k, i <= j <= k  (816 features, lexicographic)
    #pragma unroll 1
    for (int i = 0; i < 16; i++) {
        float zi = zs[i];
        #pragma unroll 1
        for (int j = i; j < 16; j++) {
            const float p = zi * zs[j];
            int k = j;
            // 4-wide software pipeline: products computed ahead of the FFMA2 stream
            for (; k + 4 <= 16; k += 4) {
                float p0 = p * zs[k + 0];
                float p1 = p * zs[k + 1];
                float p2 = p * zs[k + 2];
                float p3 = p * zs[k + 3];
                fma8(acc, p0, cp);           cp += NODE;
                fma8(acc, p1, cp);           cp += NODE;
                fma8(acc, p2, cp);           cp += NODE;
                fma8(acc, p3, cp);           cp += NODE;
            }
            for (; k < 16; k++) { fma8(acc, p * zs[k], cp); cp += NODE; }
        }
    }

    // write 16 outputs
    float4* orow = reinterpret_cast<float4*>(out + (size_t)row * 16);
    #pragma unroll
    for (int h = 0; h < 4; h++) {
        float2 a = *reinterpret_cast<float2*>(&acc[2*h]);
        float2 b = *reinterpret_cast<float2*>(&acc[2*h + 1]);
        orow[h] = make_float4(a.x, a.y, b.x, b.y);
    }
}

__global__ void l1_loss_kernel(const float* __restrict__ coef,
                               const float* __restrict__ mask,
                               float* __restrict__ outp)
{
    __shared__ float red[32];
    float s = 0.f;
    for (int idx = threadIdx.x; idx < LIB * NODE; idx += blockDim.x)
        s += fabsf(coef[idx] * mask[idx]);
    #pragma unroll
    for (int o = 16; o; o >>= 1) s += __shfl_xor_sync(0xFFFFFFFFu, s, o);
    if ((threadIdx.x & 31) == 0) red[threadIdx.x >> 5] = s;
    __syncthreads();
    if (threadIdx.x < 32) {
        float v = (threadIdx.x < (blockDim.x >> 5)) ? red[threadIdx.x] : 0.f;
        #pragma unroll
        for (int o = 16; o; o >>= 1) v += __shfl_xor_sync(0xFFFFFFFFu, v, o);
        if (threadIdx.x == 0) *outp = v / (float)(LIB * NODE);
    }
}

extern "C" void kernel_launch(void* const* d_in, const int* in_sizes, int n_in,
                              void* d_out, int out_size)
{
    const float* z    = (const float*)d_in[0];   // (N, 16) fp32
    const float* coef = (const float*)d_in[1];   // (969, 16) fp32
    const float* mask = (const float*)d_in[2];   // (969, 16) fp32
    float* out = (float*)d_out;

    const int N = in_sizes[0] / 16;
    const size_t smem_bytes = (size_t)(LIB * NODE + NT * ZSTRIDE) * sizeof(float);

    cudaFuncSetAttribute(sindy_main_kernel,
                         cudaFuncAttributeMaxDynamicSharedMemorySize, (int)smem_bytes);

    sindy_main_kernel<<<(N + NT - 1) / NT, NT, smem_bytes>>>(z, coef, mask, out, N);
    l1_loss_kernel<<<1, 256>>>(coef, mask, out + (out_size - 1));
}

// round 4
// speedup vs baseline: 1.0781x; 1.0781x over previous
#include <cuda_runtime.h>
#include <cuda_bf16.h>

#define LIB   969          // 1 + 16 + 136 + 816
#define NODE  16
#define NT    128
#define RPT   2
#define ROWS_PER_CTA (NT * RPT)   // 256
#define ZS    17                  // u64 stride: 136B -> conflict-free LDS.64

typedef unsigned long long u64;

__device__ __forceinline__ u64 mul2(u64 a, u64 b) {
    u64 r; asm("mul.rn.f32x2 %0, %1, %2;" : "=l"(r) : "l"(a), "l"(b)); return r;
}
__device__ __forceinline__ void fma2(u64& acc, u64 a, u64 b) {
    asm("fma.rn.f32x2 %0, %1, %2, %0;" : "+l"(acc) : "l"(a), "l"(b));
}

// 16 packed FMAs: two rows' 16-wide accumulators += v{0,1} * coeff_row[0..15]
// Coefficient LDS.128s (warp-uniform broadcast) amortized across both rows.
__device__ __forceinline__ void fma16(u64 a0[8], u64 a1[8], u64 v0, u64 v1,
                                      const float* cp) {
    const ulonglong2* c2 = reinterpret_cast<const ulonglong2*>(cp);
    #pragma unroll
    for (int h = 0; h < 4; h++) {
        ulonglong2 c = c2[h];
        fma2(a0[2*h],     v0, c.x);  fma2(a1[2*h],     v1, c.x);
        fma2(a0[2*h + 1], v0, c.y);  fma2(a1[2*h + 1], v1, c.y);
    }
}

extern __shared__ float smem_dyn[];

__global__ void __launch_bounds__(NT)
sindy_fused_kernel(const float* __restrict__ z,
                   const float* __restrict__ coef,
                   const float* __restrict__ mask,
                   float* __restrict__ out, int N, int out_last)
{
    float* sC  = smem_dyn;                                      // 15504 floats (60.6 KB)
    u64*   sZZ = reinterpret_cast<u64*>(smem_dyn + LIB * NODE); // NT*RPT*ZS u64 (34.8 KB)

    // ---- stage masked coefficients; fold in L1 partial sum ----
    float l1p = 0.f;
    for (int idx = threadIdx.x; idx < LIB * NODE; idx += NT) {
        float v = coef[idx] * mask[idx];
        sC[idx] = v;
        l1p += fabsf(v);
    }

    // ---- load z for my 2 rows, pack {z,z} into smem ----
    const int row0 = blockIdx.x * ROWS_PER_CTA + threadIdx.x;
    const int row1 = row0 + NT;
    u64* zz0 = sZZ + threadIdx.x * ZS;
    u64* zz1 = sZZ + (NT + threadIdx.x) * ZS;

    {
        const int lr0 = row0 < N ? row0 : 0;
        const int lr1 = row1 < N ? row1 : 0;
        const float4* zr0 = reinterpret_cast<const float4*>(z + (size_t)lr0 * 16);
        const float4* zr1 = reinterpret_cast<const float4*>(z + (size_t)lr1 * 16);
        #pragma unroll
        for (int q = 0; q < 4; q++) {
            float4 t0 = zr0[q], t1 = zr1[q];
            u64 p;
            asm("mov.b64 %0, {%1, %1};" : "=l"(p) : "f"(t0.x)); zz0[4*q+0] = p;
            asm("mov.b64 %0, {%1, %1};" : "=l"(p) : "f"(t0.y)); zz0[4*q+1] = p;
            asm("mov.b64 %0, {%1, %1};" : "=l"(p) : "f"(t0.z)); zz0[4*q+2] = p;
            asm("mov.b64 %0, {%1, %1};" : "=l"(p) : "f"(t0.w)); zz0[4*q+3] = p;
            asm("mov.b64 %0, {%1, %1};" : "=l"(p) : "f"(t1.x)); zz1[4*q+0] = p;
            asm("mov.b64 %0, {%1, %1};" : "=l"(p) : "f"(t1.y)); zz1[4*q+1] = p;
            asm("mov.b64 %0, {%1, %1};" : "=l"(p) : "f"(t1.z)); zz1[4*q+2] = p;
            asm("mov.b64 %0, {%1, %1};" : "=l"(p) : "f"(t1.w)); zz1[4*q+3] = p;
        }
    }
    __syncthreads();

    // ---- block 0: finish L1 reduction (overlapped with other blocks' compute) ----
    if (blockIdx.x == 0) {
        __shared__ float red[NT / 32];
        #pragma unroll
        for (int o = 16; o; o >>= 1) l1p += __shfl_xor_sync(0xFFFFFFFFu, l1p, o);
        if ((threadIdx.x & 31) == 0) red[threadIdx.x >> 5] = l1p;
        __syncthreads();
        if (threadIdx.x == 0) {
            float s = 0.f;
            #pragma unroll
            for (int w = 0; w < NT / 32; w++) s += red[w];
            out[out_last] = s / (float)(LIB * NODE);
        }
    }

    // ---- accumulators = constant-feature coefficient row ----
    u64 acc0[8], acc1[8];
    {
        const ulonglong2* c0 = reinterpret_cast<const ulonglong2*>(sC);
        #pragma unroll
        for (int h = 0; h < 4; h++) {
            ulonglong2 c = c0[h];
            acc0[2*h] = c.x; acc1[2*h] = c.x;
            acc0[2*h+1] = c.y; acc1[2*h+1] = c.y;
        }
    }

    const float* cp = sC + NODE;

    // linear: z_i
    #pragma unroll 1
    for (int i = 0; i < 16; i++) {
        fma16(acc0, acc1, zz0[i], zz1[i], cp); cp += NODE;
    }

    // pairs: z_i z_j, i<=j (lexicographic, matches np.triu_indices)
    #pragma unroll 1
    for (int i = 0; i < 16; i++) {
        const u64 a0 = zz0[i], a1 = zz1[i];
        #pragma unroll 2
        for (int j = i; j < 16; j++) {
            fma16(acc0, acc1, mul2(a0, zz0[j]), mul2(a1, zz1[j]), cp); cp += NODE;
        }
    }

    // triples: z_i z_j z_k, i<=j<=k (lexicographic)
    #pragma unroll 1
    for (int i = 0; i < 16; i++) {
        const u64 a0 = zz0[i], a1 = zz1[i];
        #pragma unroll 1
        for (int j = i; j < 16; j++) {
            const u64 p0 = mul2(a0, zz0[j]);
            const u64 p1 = mul2(a1, zz1[j]);
            #pragma unroll 2
            for (int k = j; k < 16; k++) {
                fma16(acc0, acc1, mul2(p0, zz0[k]), mul2(p1, zz1[k]), cp); cp += NODE;
            }
        }
    }

    // ---- write 2x16 outputs ----
    if (row0 < N) {
        float4* o = reinterpret_cast<float4*>(out + (size_t)row0 * 16);
        #pragma unroll
        for (int h = 0; h < 4; h++) {
            float2 a = *reinterpret_cast<float2*>(&acc0[2*h]);
            float2 b = *reinterpret_cast<float2*>(&acc0[2*h + 1]);
            o[h] = make_float4(a.x, a.y, b.x, b.y);
        }
    }
    if (row1 < N) {
        float4* o = reinterpret_cast<float4*>(out + (size_t)row1 * 16);
        #pragma unroll
        for (int h = 0; h < 4; h++) {
            float2 a = *reinterpret_cast<float2*>(&acc1[2*h]);
            float2 b = *reinterpret_cast<float2*>(&acc1[2*h + 1]);
            o[h] = make_float4(a.x, a.y, b.x, b.y);
        }
    }
}

extern "C" void kernel_launch(void* const* d_in, const int* in_sizes, int n_in,
                              void* d_out, int out_size)
{
    const float* z    = (const float*)d_in[0];   // (N, 16) fp32
    const float* coef = (const float*)d_in[1];   // (969, 16) fp32
    const float* mask = (const float*)d_in[2];   // (969, 16) fp32
    float* out = (float*)d_out;

    const int N = in_sizes[0] / 16;
    const int grid = (N + ROWS_PER_CTA - 1) / ROWS_PER_CTA;
    const size_t smem_bytes = (size_t)LIB * NODE * sizeof(float)
                            + (size_t)NT * RPT * ZS * sizeof(u64);

    cudaFuncSetAttribute(sindy_fused_kernel,
                         cudaFuncAttributeMaxDynamicSharedMemorySize, (int)smem_bytes);

    sindy_fused_kernel<<<grid, NT, smem_bytes>>>(z, coef, mask, out, N, out_size - 1);
}

// round 5
// speedup vs baseline: 1.1833x; 1.0976x over previous
#include <cuda_runtime.h>
#include <cuda_bf16.h>

#define LIB   969          // 1 + 16 + 136 + 816
#define NODE  16
#define NT    128
#define RPT   2
#define ROWS_PER_CTA (NT * RPT)   // 256

typedef unsigned long long u64;

__device__ __forceinline__ u64 mul2(u64 a, u64 b) {
    u64 r; asm("mul.rn.f32x2 %0, %1, %2;" : "=l"(r) : "l"(a), "l"(b)); return r;
}
__device__ __forceinline__ void fma2(u64& acc, u64 a, u64 b) {
    asm("fma.rn.f32x2 %0, %1, %2, %0;" : "+l"(acc) : "l"(a), "l"(b));
}
__device__ __forceinline__ u64 pack2(float v) {
    u64 p; asm("mov.b64 %0, {%1, %1};" : "=l"(p) : "f"(v)); return p;
}

// 16 packed FMAs: two rows' 16-wide accumulators += v{0,1} * coeff_row[0..15]
// Coefficient LDS.128s (warp-uniform broadcast) amortized across both rows.
__device__ __forceinline__ void fma16(u64 a0[8], u64 a1[8], u64 v0, u64 v1,
                                      const float* cp) {
    const ulonglong2* c2 = reinterpret_cast<const ulonglong2*>(cp);
    #pragma unroll
    for (int h = 0; h < 4; h++) {
        ulonglong2 c = c2[h];
        fma2(a0[2*h],     v0, c.x);  fma2(a1[2*h],     v1, c.x);
        fma2(a0[2*h + 1], v0, c.y);  fma2(a1[2*h + 1], v1, c.y);
    }
}

extern __shared__ float smem_dyn[];   // coefficients only: 60.6 KB -> 3 CTAs/SM

__global__ void __launch_bounds__(NT, 3)
sindy_fused_kernel(const float* __restrict__ z,
                   const float* __restrict__ coef,
                   const float* __restrict__ mask,
                   float* __restrict__ out, int N, int out_last)
{
    float* sC = smem_dyn;   // LIB*NODE = 15504 floats

    // ---- stage masked coefficients; fold in L1 partial sum ----
    float l1p = 0.f;
    for (int idx = threadIdx.x; idx < LIB * NODE; idx += NT) {
        float v = coef[idx] * mask[idx];
        sC[idx] = v;
        l1p += fabsf(v);
    }

    // ---- load z for my 2 rows into REGISTERS, packed {z,z} ----
    const int row0 = blockIdx.x * ROWS_PER_CTA + threadIdx.x;
    const int row1 = row0 + NT;
    u64 zz0[16], zz1[16];
    {
        const int lr0 = row0 < N ? row0 : 0;
        const int lr1 = row1 < N ? row1 : 0;
        const float4* zr0 = reinterpret_cast<const float4*>(z + (size_t)lr0 * 16);
        const float4* zr1 = reinterpret_cast<const float4*>(z + (size_t)lr1 * 16);
        #pragma unroll
        for (int q = 0; q < 4; q++) {
            float4 t0 = zr0[q], t1 = zr1[q];
            zz0[4*q+0] = pack2(t0.x); zz0[4*q+1] = pack2(t0.y);
            zz0[4*q+2] = pack2(t0.z); zz0[4*q+3] = pack2(t0.w);
            zz1[4*q+0] = pack2(t1.x); zz1[4*q+1] = pack2(t1.y);
            zz1[4*q+2] = pack2(t1.z); zz1[4*q+3] = pack2(t1.w);
        }
    }
    __syncthreads();

    // ---- block 0: finish L1 reduction (overlapped with other blocks' compute) ----
    if (blockIdx.x == 0) {
        __shared__ float red[NT / 32];
        float s = l1p;
        #pragma unroll
        for (int o = 16; o; o >>= 1) s += __shfl_xor_sync(0xFFFFFFFFu, s, o);
        if ((threadIdx.x & 31) == 0) red[threadIdx.x >> 5] = s;
        __syncthreads();
        if (threadIdx.x == 0) {
            float t = 0.f;
            #pragma unroll
            for (int w = 0; w < NT / 32; w++) t += red[w];
            out[out_last] = t / (float)(LIB * NODE);
        }
    }

    // ---- accumulators = constant-feature coefficient row ----
    u64 acc0[8], acc1[8];
    {
        const ulonglong2* c0 = reinterpret_cast<const ulonglong2*>(sC);
        #pragma unroll
        for (int h = 0; h < 4; h++) {
            ulonglong2 c = c0[h];
            acc0[2*h]   = c.x; acc1[2*h]   = c.x;
            acc0[2*h+1] = c.y; acc1[2*h+1] = c.y;
        }
    }

    const float* cp = sC + NODE;

    // linear: z_i  (fully unrolled; z operands are registers)
    #pragma unroll
    for (int i = 0; i < 16; i++) {
        fma16(acc0, acc1, zz0[i], zz1[i], cp); cp += NODE;
    }

    // pairs: z_i z_j, i<=j (lexicographic, matches np.triu_indices)
    #pragma unroll
    for (int i = 0; i < 16; i++) {
        #pragma unroll
        for (int j = i; j < 16; j++) {
            fma16(acc0, acc1, mul2(zz0[i], zz0[j]), mul2(zz1[i], zz1[j]), cp);
            cp += NODE;
        }
    }

    // triples: z_i z_j z_k, i<=j<=k (lexicographic)
    #pragma unroll
    for (int i = 0; i < 16; i++) {
        #pragma unroll
        for (int j = i; j < 16; j++) {
            const u64 p0 = mul2(zz0[i], zz0[j]);
            const u64 p1 = mul2(zz1[i], zz1[j]);
            #pragma unroll
            for (int k = j; k < 16; k++) {
                fma16(acc0, acc1, mul2(p0, zz0[k]), mul2(p1, zz1[k]), cp);
                cp += NODE;
            }
        }
    }

    // ---- write 2x16 outputs ----
    if (row0 < N) {
        float4* o = reinterpret_cast<float4*>(out + (size_t)row0 * 16);
        #pragma unroll
        for (int h = 0; h < 4; h++) {
            float2 a = *reinterpret_cast<float2*>(&acc0[2*h]);
            float2 b = *reinterpret_cast<float2*>(&acc0[2*h + 1]);
            o[h] = make_float4(a.x, a.y, b.x, b.y);
        }
    }
    if (row1 < N) {
        float4* o = reinterpret_cast<float4*>(out + (size_t)row1 * 16);
        #pragma unroll
        for (int h = 0; h < 4; h++) {
            float2 a = *reinterpret_cast<float2*>(&acc1[2*h]);
            float2 b = *reinterpret_cast<float2*>(&acc1[2*h + 1]);
            o[h] = make_float4(a.x, a.y, b.x, b.y);
        }
    }
}

extern "C" void kernel_launch(void* const* d_in, const int* in_sizes, int n_in,
                              void* d_out, int out_size)
{
    const float* z    = (const float*)d_in[0];   // (N, 16) fp32
    const float* coef = (const float*)d_in[1];   // (969, 16) fp32
    const float* mask = (const float*)d_in[2];   // (969, 16) fp32
    float* out = (float*)d_out;

    const int N = in_sizes[0] / 16;
    const int grid = (N + ROWS_PER_CTA - 1) / ROWS_PER_CTA;
    const size_t smem_bytes = (size_t)LIB * NODE * sizeof(float);

    cudaFuncSetAttribute(sindy_fused_kernel,
                         cudaFuncAttributeMaxDynamicSharedMemorySize, (int)smem_bytes);

    sindy_fused_kernel<<<grid, NT, smem_bytes>>>(z, coef, mask, out, N, out_size - 1);
}

// round 7
// speedup vs baseline: 1.4456x; 1.2216x over previous
#include <cuda_runtime.h>
#include <cuda_bf16.h>
#include <cstdint>

#define LIB    969          // 1 + 16 + 136 + 816
#define KPAD   1024         // padded K: 16 chunks of 64
#define NODE   16
#define NT     128
#define TILE_M 128

// dynamic smem layout (bytes)
#define OFF_AH 0                 // theta_hi chunk: 128 x 64 bf16 = 16 KB (SW128 rows)
#define OFF_AM 16384             // theta_lo chunk: 16 KB
#define OFF_BH 32768             // C_hi: 16 chunks x (16 x 64 bf16 = 2 KB) = 32 KB
#define OFF_BM 65536             // C_lo: 32 KB
#define SMEM_TOTAL 98304         // 96 KB -> 2 CTAs/SM

typedef unsigned int u32;

__device__ __forceinline__ u32 smem_u32_of(const void* p) {
    u32 a; asm("{ .reg .u64 t; cvta.to.shared.u64 t, %1; cvt.u32.u64 %0, t; }" : "=r"(a) : "l"(p));
    return a;
}
__device__ __forceinline__ u32 swz(u32 off) { return off ^ ((off >> 3) & 0x70); }

// pack 2 fp32 -> bf16x2; d.hi = a(hi arg), d.lo = b(lo arg)
__device__ __forceinline__ u32 bf2(float hi, float lo) {
    u32 r; asm("cvt.rn.bf16x2.f32 %0, %1, %2;" : "=r"(r) : "f"(hi), "f"(lo)); return r;
}
__device__ __forceinline__ void ldm4(u32 r[4], u32 addr) {
    asm volatile("ldmatrix.sync.aligned.m8n8.x4.shared.b16 {%0,%1,%2,%3}, [%4];"
                 : "=r"(r[0]), "=r"(r[1]), "=r"(r[2]), "=r"(r[3]) : "r"(addr));
}
__device__ __forceinline__ void hmma(float c[4], const u32 a[4], u32 b0, u32 b1) {
    asm volatile("mma.sync.aligned.m16n8k16.row.col.f32.bf16.bf16.f32 "
                 "{%0,%1,%2,%3}, {%4,%5,%6,%7}, {%8,%9}, {%0,%1,%2,%3};"
                 : "+f"(c[0]), "+f"(c[1]), "+f"(c[2]), "+f"(c[3])
                 : "r"(a[0]), "r"(a[1]), "r"(a[2]), "r"(a[3]), "r"(b0), "r"(b1));
}

extern __shared__ char smem[];

// Consume chunk c: 4 k-steps of m16n8k16, 3-product bf16 split (Ah*Bh + Ah*Bl + Al*Bh).
__device__ __forceinline__ void mma_chunk(int c, int lane, int wid, u32 sb,
                                          float acc[2][2][4])
{
    // ldmatrix address bases (per-thread): 8 addrs per 8x8 matrix, x4 ordering:
    //   A: m0=(rows0-7,k0-7) m1=(rows8-15,k0-7) m2=(rows0-7,k8-15) m3=(rows8-15,k8-15)
    //   B: same with rows := n
    const u32 aBase = (u32)(32 * wid + (lane & 7) + ((lane >> 3) & 1) * 8) * 128u
                    + ((lane >> 4) & 1) * 16u;
    const u32 bBase = (u32)((lane & 7) + ((lane >> 3) & 1) * 8) * 128u
                    + ((lane >> 4) & 1) * 16u + (u32)c * 2048u;

    #pragma unroll
    for (int ks = 0; ks < 4; ks++) {
        const u32 kb = (u32)ks * 32u;
        u32 bh[4], bl[4];
        ldm4(bh, sb + OFF_BH + swz(bBase + kb));
        ldm4(bl, sb + OFF_BM + swz(bBase + kb));
        #pragma unroll
        for (int mt = 0; mt < 2; mt++) {
            u32 ah[4], al[4];
            const u32 aoff = aBase + (u32)mt * 2048u + kb;   // 16 rows * 128 B
            ldm4(ah, sb + OFF_AH + swz(aoff));
            ldm4(al, sb + OFF_AM + swz(aoff));
            hmma(acc[mt][0], ah, bh[0], bh[2]);
            hmma(acc[mt][1], ah, bh[1], bh[3]);
            hmma(acc[mt][0], al, bh[0], bh[2]);
            hmma(acc[mt][1], al, bh[1], bh[3]);
            hmma(acc[mt][0], ah, bl[0], bl[2]);
            hmma(acc[mt][1], ah, bl[1], bl[3]);
        }
    }
}

__global__ void __launch_bounds__(NT)
sindy_tc_kernel(const float* __restrict__ z,
                const float* __restrict__ coef,
                const float* __restrict__ mask,
                float* __restrict__ out, int N, int out_last)
{
    const int tid  = threadIdx.x;
    const int lane = tid & 31;
    const int wid  = tid >> 5;
    const u32 sb = smem_u32_of(smem);

    // ---- build B = C^T (masked), bf16 hi + residual lo, K-major SW128, 64-wide chunks ----
    float l1p = 0.f;
    for (int e = tid; e < KPAD * NODE; e += NT) {
        const int k = e >> 4, n = e & 15;
        float v = 0.f;
        if (k < LIB) v = coef[k * NODE + n] * mask[k * NODE + n];
        l1p += fabsf(v);
        __nv_bfloat16 h = __float2bfloat16(v);
        __nv_bfloat16 m = __float2bfloat16(v - __bfloat162float(h));
        const u32 boff = (u32)(k >> 6) * 2048u + swz((u32)n * 128u + (u32)(k & 63) * 2u);
        *reinterpret_cast<__nv_bfloat16*>(smem + OFF_BH + boff) = h;
        *reinterpret_cast<__nv_bfloat16*>(smem + OFF_BM + boff) = m;
    }

    // ---- load z row (thread tid owns tile row tid) ----
    const int row = blockIdx.x * TILE_M + tid;
    float zr[16];
    {
        const int lr = row < N ? row : N - 1;
        const float4* zp = reinterpret_cast<const float4*>(z + (size_t)lr * 16);
        #pragma unroll
        for (int q = 0; q < 4; q++) {
            float4 t = zp[q];
            zr[4*q+0] = t.x; zr[4*q+1] = t.y; zr[4*q+2] = t.z; zr[4*q+3] = t.w;
        }
    }
    __syncthreads();   // B visible

    // ---- block 0: L1 scalar (overlapped with other blocks' compute) ----
    if (blockIdx.x == 0) {
        __shared__ float red[NT / 32];
        float s = l1p;
        #pragma unroll
        for (int o = 16; o; o >>= 1) s += __shfl_xor_sync(0xFFFFFFFFu, s, o);
        if (lane == 0) red[wid] = s;
        __syncthreads();
        if (tid == 0) {
            float t = 0.f;
            #pragma unroll
            for (int w = 0; w < NT / 32; w++) t += red[w];
            out[out_last] = t / (float)(LIB * NODE);
        }
    }

    float acc[2][2][4];
    #pragma unroll
    for (int a = 0; a < 2; a++)
        #pragma unroll
        for (int b = 0; b < 2; b++)
            #pragma unroll
            for (int q = 0; q < 4; q++) acc[a][b][q] = 0.f;

    // ---- fused theta build + MMA, 16 chunks of 64 features ----
    const u32 rowbase = (u32)tid * 128u;
    float fb[8];
    int fcnt = 0;

#define FLUSH8() do {                                                                  \
        u32 h0 = bf2(fb[1], fb[0]), h1 = bf2(fb[3], fb[2]);                            \
        u32 h2 = bf2(fb[5], fb[4]), h3 = bf2(fb[7], fb[6]);                            \
        float r0 = fb[0] - __uint_as_float(h0 << 16);                                  \
        float r1 = fb[1] - __uint_as_float(h0 & 0xFFFF0000u);                          \
        float r2 = fb[2] - __uint_as_float(h1 << 16);                                  \
        float r3 = fb[3] - __uint_as_float(h1 & 0xFFFF0000u);                          \
        float r4 = fb[4] - __uint_as_float(h2 << 16);                                  \
        float r5 = fb[5] - __uint_as_float(h2 & 0xFFFF0000u);                          \
        float r6 = fb[6] - __uint_as_float(h3 << 16);                                  \
        float r7 = fb[7] - __uint_as_float(h3 & 0xFFFF0000u);                          \
        u32 m0 = bf2(r1, r0), m1 = bf2(r3, r2), m2 = bf2(r5, r4), m3 = bf2(r7, r6);    \
        const u32 aoff = swz(rowbase + (u32)((fcnt >> 3) & 7) * 16u);                  \
        *reinterpret_cast<uint4*>(smem + OFF_AH + aoff) = make_uint4(h0, h1, h2, h3);  \
        *reinterpret_cast<uint4*>(smem + OFF_AM + aoff) = make_uint4(m0, m1, m2, m3);  \
    } while (0)

#define CHUNK_MMA() do {                                                               \
        const int c = fcnt >> 6;                                                       \
        __syncthreads();                                                               \
        mma_chunk(c, lane, wid, sb, acc);                                              \
        __syncthreads();                                                               \
    } while (0)

#define EMIT(v) do {                                                                   \
        fb[fcnt & 7] = (v);                                                            \
        if ((fcnt & 7) == 7)   FLUSH8();                                               \
        if ((fcnt & 63) == 63) CHUNK_MMA();                                            \
        fcnt++;                                                                        \
    } while (0)

    EMIT(1.0f);
    #pragma unroll
    for (int i = 0; i < 16; i++) EMIT(zr[i]);
    #pragma unroll
    for (int i = 0; i < 16; i++)
        #pragma unroll
        for (int j = i; j < 16; j++) EMIT(zr[i] * zr[j]);
    #pragma unroll
    for (int i = 0; i < 16; i++)
        #pragma unroll
        for (int j = i; j < 16; j++) {
            const float p = zr[i] * zr[j];
            #pragma unroll
            for (int k = j; k < 16; k++) EMIT(p * zr[k]);
        }
    #pragma unroll
    for (int t = 0; t < KPAD - LIB; t++) EMIT(0.0f);
    // fcnt == 1024: all 16 chunks consumed

    // ---- write fragments: warp w rows 32w+16mt+g(+8), cols 8nt+2t(+1) ----
    const int rbase = blockIdx.x * TILE_M + 32 * wid;
    const int g = lane >> 2, t2 = 2 * (lane & 3);
    #pragma unroll
    for (int mt = 0; mt < 2; mt++)
        #pragma unroll
        for (int half = 0; half < 2; half++) {
            const int r = rbase + 16 * mt + g + half * 8;
            if (r < N) {
                #pragma unroll
                for (int nt = 0; nt < 2; nt++) {
                    float2 v = make_float2(acc[mt][nt][half*2 + 0], acc[mt][nt][half*2 + 1]);
                    *reinterpret_cast<float2*>(out + (size_t)r * 16 + 8*nt + t2) = v;
                }
            }
        }

#undef EMIT
#undef CHUNK_MMA
#undef FLUSH8
}

extern "C" void kernel_launch(void* const* d_in, const int* in_sizes, int n_in,
                              void* d_out, int out_size)
{
    const float* z    = (const float*)d_in[0];   // (N, 16) fp32
    const float* coef = (const float*)d_in[1];   // (969, 16) fp32
    const float* mask = (const float*)d_in[2];   // (969, 16) fp32
    float* out = (float*)d_out;

    const int N = in_sizes[0] / 16;              // 262144
    const int grid = (N + TILE_M - 1) / TILE_M;  // 2048

    cudaFuncSetAttribute(sindy_tc_kernel,
                         cudaFuncAttributeMaxDynamicSharedMemorySize, SMEM_TOTAL);

    sindy_tc_kernel<<<grid, NT, SMEM_TOTAL>>>(z, coef, mask, out, N, out_size - 1);
}

// round 9
// speedup vs baseline: 1.8627x; 1.2886x over previous
#include <cuda_runtime.h>
#include <cuda_fp16.h>
#include <cstdint>

#define LIB    969          // 1 + 16 + 136 + 816
#define KPAD   1024         // padded K: 16 chunks of 64
#define NODE   16
#define NT     128
#define TILE_M 128

// dynamic smem layout (bytes)
#define OFF_A0 0                 // theta chunk buf0: 128 x 64 fp16 = 16 KB (SW128 rows)
#define OFF_A1 16384             // theta chunk buf1: 16 KB
#define OFF_BH 32768             // C_hi: 16 chunks x (16 x 64 fp16 = 2 KB) = 32 KB
#define OFF_BL 65536             // C_lo (residual): 32 KB
#define SMEM_TOTAL 98304         // 96 KB -> 2 CTAs/SM

typedef unsigned int u32;

__device__ __forceinline__ u32 smem_u32_of(const void* p) {
    u32 a; asm("{ .reg .u64 t; cvta.to.shared.u64 t, %1; cvt.u32.u64 %0, t; }" : "=r"(a) : "l"(p));
    return a;
}
__device__ __forceinline__ u32 swz(u32 off) { return off ^ ((off >> 3) & 0x70); }

// pack 2 fp32 -> fp16x2; result.hi = first arg, result.lo = second arg
__device__ __forceinline__ u32 f2h2(float hi, float lo) {
    u32 r; asm("cvt.rn.f16x2.f32 %0, %1, %2;" : "=r"(r) : "f"(hi), "f"(lo)); return r;
}
__device__ __forceinline__ void ldm4(u32 r[4], u32 addr) {
    asm volatile("ldmatrix.sync.aligned.m8n8.x4.shared.b16 {%0,%1,%2,%3}, [%4];"
                 : "=r"(r[0]), "=r"(r[1]), "=r"(r[2]), "=r"(r[3]) : "r"(addr));
}
__device__ __forceinline__ void hmma(float c[4], const u32 a[4], u32 b0, u32 b1) {
    asm volatile("mma.sync.aligned.m16n8k16.row.col.f32.f16.f16.f32 "
                 "{%0,%1,%2,%3}, {%4,%5,%6,%7}, {%8,%9}, {%0,%1,%2,%3};"
                 : "+f"(c[0]), "+f"(c[1]), "+f"(c[2]), "+f"(c[3])
                 : "r"(a[0]), "r"(a[1]), "r"(a[2]), "r"(a[3]), "r"(b0), "r"(b1));
}

extern __shared__ char smem[];

// Consume chunk c from buffer buf: 4 k-steps of m16n8k16, 2 products (A*Bh + A*Bl).
__device__ __forceinline__ void mma_chunk(int c, int buf, int lane, int wid, u32 sb,
                                          float acc[2][2][4])
{
    const u32 aBase = (u32)(32 * wid + (lane & 7) + ((lane >> 3) & 1) * 8) * 128u
                    + ((lane >> 4) & 1) * 16u;
    const u32 bBase = (u32)((lane & 7) + ((lane >> 3) & 1) * 8) * 128u
                    + ((lane >> 4) & 1) * 16u;
    const u32 aSm = sb + (buf ? OFF_A1 : OFF_A0);
    const u32 bcs = (u32)c * 2048u;

    #pragma unroll
    for (int ks = 0; ks < 4; ks++) {
        const u32 kb = (u32)ks * 32u;
        u32 bh[4], bl[4];
        ldm4(bh, sb + OFF_BH + bcs + swz(bBase + kb));
        ldm4(bl, sb + OFF_BL + bcs + swz(bBase + kb));
        u32 a0[4], a1[4];
        ldm4(a0, aSm + swz(aBase + kb));
        ldm4(a1, aSm + swz(aBase + 2048u + kb));   // mt=1: +16 rows * 128 B
        // 4 independent acc chains first (hi), then the lo pass
        hmma(acc[0][0], a0, bh[0], bh[2]);
        hmma(acc[0][1], a0, bh[1], bh[3]);
        hmma(acc[1][0], a1, bh[0], bh[2]);
        hmma(acc[1][1], a1, bh[1], bh[3]);
        hmma(acc[0][0], a0, bl[0], bl[2]);
        hmma(acc[0][1], a0, bl[1], bl[3]);
        hmma(acc[1][0], a1, bl[0], bl[2]);
        hmma(acc[1][1], a1, bl[1], bl[3]);
    }
}

__global__ void __launch_bounds__(NT)
sindy_tc_kernel(const float* __restrict__ z,
                const float* __restrict__ coef,
                const float* __restrict__ mask,
                float* __restrict__ out, int N, int out_last)
{
    const int tid  = threadIdx.x;
    const int lane = tid & 31;
    const int wid  = tid >> 5;
    const u32 sb = smem_u32_of(smem);

    // ---- build B = C^T (masked): fp16 hi + fp16 residual, K-major SW128, 64-wide chunks ----
    float l1p = 0.f;
    for (int e = tid; e < KPAD * NODE; e += NT) {
        const int k = e >> 4, n = e & 15;
        float v = 0.f;
        if (k < LIB) v = coef[k * NODE + n] * mask[k * NODE + n];
        l1p += fabsf(v);
        __half h = __float2half_rn(v);
        __half l = __float2half_rn(v - __half2float(h));
        const u32 boff = (u32)(k >> 6) * 2048u + swz((u32)n * 128u + (u32)(k & 63) * 2u);
        *reinterpret_cast<__half*>(smem + OFF_BH + boff) = h;
        *reinterpret_cast<__half*>(smem + OFF_BL + boff) = l;
    }

    // ---- load z row (thread tid owns tile row tid) ----
    const int row = blockIdx.x * TILE_M + tid;
    float zr[16];
    {
        const int lr = row < N ? row : N - 1;
        const float4* zp = reinterpret_cast<const float4*>(z + (size_t)lr * 16);
        #pragma unroll
        for (int q = 0; q < 4; q++) {
            float4 t = zp[q];
            zr[4*q+0] = t.x; zr[4*q+1] = t.y; zr[4*q+2] = t.z; zr[4*q+3] = t.w;
        }
    }
    __syncthreads();   // B visible (also orders the L1 block below)

    // ---- block 0: L1 scalar (overlapped with other blocks' compute) ----
    if (blockIdx.x == 0) {
        __shared__ float red[NT / 32];
        float s = l1p;
        #pragma unroll
        for (int o = 16; o; o >>= 1) s += __shfl_xor_sync(0xFFFFFFFFu, s, o);
        if (lane == 0) red[wid] = s;
        __syncthreads();
        if (tid == 0) {
            float t = 0.f;
            #pragma unroll
            for (int w = 0; w < NT / 32; w++) t += red[w];
            out[out_last] = t / (float)(LIB * NODE);
        }
    }

    float acc[2][2][4];
    #pragma unroll
    for (int a = 0; a < 2; a++)
        #pragma unroll
        for (int b = 0; b < 2; b++)
            #pragma unroll
            for (int q = 0; q < 4; q++) acc[a][b][q] = 0.f;

    // ---- fused theta build + MMA, 16 chunks of 64 features, double-buffered A ----
    // Chunk c is built into buf (c&1); at chunk end: one __syncthreads, then MMA(c).
    // Build of c+1 (next EMITs) and MMA(c) share a sync-free region -> ptxas interleaves.
    // buf(c&1) is safely rewritten at c+2 (one full sync separates MMA read / next write).
    const u32 rowbase = (u32)tid * 128u;
    float fb[8];
    int fcnt = 0;

#define FLUSH8() do {                                                                  \
        u32 h0 = f2h2(fb[1], fb[0]), h1 = f2h2(fb[3], fb[2]);                          \
        u32 h2 = f2h2(fb[5], fb[4]), h3 = f2h2(fb[7], fb[6]);                          \
        const u32 bo = ((fcnt >> 6) & 1) ? OFF_A1 : OFF_A0;                            \
        const u32 aoff = bo + swz(rowbase + (u32)((fcnt >> 3) & 7) * 16u);             \
        *reinterpret_cast<uint4*>(smem + aoff) = make_uint4(h0, h1, h2, h3);           \
    } while (0)

#define CHUNK_MMA() do {                                                               \
        const int c = fcnt >> 6;                                                       \
        __syncthreads();                                                               \
        mma_chunk(c, c & 1, lane, wid, sb, acc);                                       \
    } while (0)

#define EMIT(v) do {                                                                   \
        fb[fcnt & 7] = (v);                                                            \
        if ((fcnt & 7) == 7)   FLUSH8();                                               \
        if ((fcnt & 63) == 63) CHUNK_MMA();                                            \
        fcnt++;                                                                        \
    } while (0)

    EMIT(1.0f);
    #pragma unroll
    for (int i = 0; i < 16; i++) EMIT(zr[i]);
    #pragma unroll
    for (int i = 0; i < 16; i++)
        #pragma unroll
        for (int j = i; j < 16; j++) EMIT(zr[i] * zr[j]);
    #pragma unroll
    for (int i = 0; i < 16; i++)
        #pragma unroll
        for (int j = i; j < 16; j++) {
            const float p = zr[i] * zr[j];
            #pragma unroll
            for (int k = j; k < 16; k++) EMIT(p * zr[k]);
        }
    #pragma unroll
    for (int t = 0; t < KPAD - LIB; t++) EMIT(0.0f);
    // fcnt == 1024: all 16 chunks built and consumed (MMA(15) issued after last sync)

    // ---- write fragments: warp w rows 32w+16mt+g(+8), cols 8nt+2t(+1) ----
    const int rbase = blockIdx.x * TILE_M + 32 * wid;
    const int g = lane >> 2, t2 = 2 * (lane & 3);
    #pragma unroll
    for (int mt = 0; mt < 2; mt++)
        #pragma unroll
        for (int half = 0; half < 2; half++) {
            const int r = rbase + 16 * mt + g + half * 8;
            if (r < N) {
                #pragma unroll
                for (int nt = 0; nt < 2; nt++) {
                    float2 v = make_float2(acc[mt][nt][half*2 + 0], acc[mt][nt][half*2 + 1]);
                    *reinterpret_cast<float2*>(out + (size_t)r * 16 + 8*nt + t2) = v;
                }
            }
        }

#undef EMIT
#undef CHUNK_MMA
#undef FLUSH8
}

extern "C" void kernel_launch(void* const* d_in, const int* in_sizes, int n_in,
                              void* d_out, int out_size)
{
    const float* z    = (const float*)d_in[0];   // (N, 16) fp32
    const float* coef = (const float*)d_in[1];   // (969, 16) fp32
    const float* mask = (const float*)d_in[2];   // (969, 16) fp32
    float* out = (float*)d_out;

    const int N = in_sizes[0] / 16;              // 262144
    const int grid = (N + TILE_M - 1) / TILE_M;  // 2048

    cudaFuncSetAttribute(sindy_tc_kernel,
                         cudaFuncAttributeMaxDynamicSharedMemorySize, SMEM_TOTAL);

    sindy_tc_kernel<<<grid, NT, SMEM_TOTAL>>>(z, coef, mask, out, N, out_size - 1);
}